// round 17
// baseline (speedup 1.0000x reference)
#include <cuda_runtime.h>
#include <cstdint>

// GNN critic encoder, fully fused: one CTA per batch row.
// R16 = R15 + (a) weight hi/lo splits precomputed once into __device__ scratch
//       (B-frag = single LDG.64, zero split ALU), (b) pbuf halved via two-phase
//       aggregation A-fragments -> smem ~27.8KB -> 7 CTAs/SM.

#define XSROW 132      // xs token-row stride: 132 % 32 == 4 -> frag reads conflict-free
#define PST   36       // pbuf row stride: 4*i+j banks -> A-frag reads conflict-free

// Precomputed weight splits: [layer][k*128 + col] = {hi, lo}
__device__ float2 g_wsplit[2][16384];

__device__ __forceinline__ float elu1(float v) { return v > 0.f ? v : expm1f(v); }

// tf32 split: hi = top 10 mantissa bits (valid tf32), lo = exact residual
__device__ __forceinline__ void split_tf32(float v, unsigned& hi, unsigned& lo) {
    unsigned u = __float_as_uint(v) & 0xFFFFE000u;
    hi = u;
    lo = __float_as_uint(v - __uint_as_float(u));
}
__device__ __forceinline__ unsigned hi_tf32(float v) {
    return __float_as_uint(v) & 0xFFFFE000u;
}

__device__ __forceinline__ void mma_tf32(float c[4],
                                         unsigned a0, unsigned a1, unsigned a2, unsigned a3,
                                         unsigned b0, unsigned b1) {
    asm volatile(
        "mma.sync.aligned.m16n8k8.row.col.f32.tf32.tf32.f32 "
        "{%0,%1,%2,%3}, {%4,%5,%6,%7}, {%8,%9}, {%0,%1,%2,%3};"
        : "+f"(c[0]), "+f"(c[1]), "+f"(c[2]), "+f"(c[3])
        : "r"(a0), "r"(a1), "r"(a2), "r"(a3), "r"(b0), "r"(b1));
}

// ---- prep: split both layer weight matrices into {hi, lo} pairs ----
__global__ void split_weights_kernel(const float* __restrict__ w0,
                                     const float* __restrict__ w1)
{
    int i = blockIdx.x * blockDim.x + threadIdx.x;
    if (i < 16384) {
        float v0 = __ldg(&w0[i]);
        unsigned h0 = __float_as_uint(v0) & 0xFFFFE000u;
        g_wsplit[0][i] = make_float2(__uint_as_float(h0), v0 - __uint_as_float(h0));
        float v1 = __ldg(&w1[i]);
        unsigned h1 = __float_as_uint(v1) & 0xFFFFE000u;
        g_wsplit[1][i] = make_float2(__uint_as_float(h1), v1 - __uint_as_float(h1));
    }
}

// Token embedding -> xs (token-major [32][XSROW]). Cols: lane, lane+32, lane+64, lane+96.
template<int D>
__device__ __forceinline__ void embed_tokens(const float* __restrict__ obs_tok,
                                             const float* __restrict__ W,
                                             const float* __restrict__ bias,
                                             float* __restrict__ xs,
                                             int t0, int lane)
{
    float bb[4];
#pragma unroll
    for (int c = 0; c < 4; c++) bb[c] = __ldg(&bias[lane + 32 * c]);
    float acc[8][4];
#pragma unroll
    for (int r = 0; r < 8; r++)
#pragma unroll
        for (int c = 0; c < 4; c++) acc[r][c] = bb[c];
#pragma unroll 4
    for (int d = 0; d < D; d++) {
        float wv[4];
#pragma unroll
        for (int c = 0; c < 4; c++) wv[c] = __ldg(&W[d * 128 + lane + 32 * c]);
#pragma unroll
        for (int r = 0; r < 8; r++) {
            float xv = obs_tok[r * D + d];
#pragma unroll
            for (int c = 0; c < 4; c++) acc[r][c] += xv * wv[c];
        }
    }
#pragma unroll
    for (int r = 0; r < 8; r++)
#pragma unroll
        for (int c = 0; c < 4; c++)
            xs[(t0 + r) * XSROW + lane + 32 * c] = acc[r][c];
}

__global__ __launch_bounds__(128, 7)
void gnn_critic_kernel(const float* __restrict__ gobs,
                       const float* __restrict__ Wv, const float* __restrict__ bv,
                       const float* __restrict__ Wp, const float* __restrict__ bp,
                       const float* __restrict__ as0, const float* __restrict__ ad0,
                       const float* __restrict__ as1, const float* __restrict__ ad1,
                       float* __restrict__ out)
{
    __shared__ float xs[32 * XSROW];                  // activations / h (head bands alias)
    __shared__ __align__(16) float pbuf[4][16][PST];  // per-head p rows (half at a time)
    __shared__ float as_sh[128];                      // [head*32 + token]
    __shared__ float ad_sh[128];
    __shared__ float inv_sh[128];                     // per (head, query) 1/sum
    __shared__ float alive[32];
    __shared__ float inv_cnt_sh;

    float* obs = &pbuf[0][0][0];                      // 1056 <= 2304; dead before softmax L0

    const int tid  = threadIdx.x;
    const int lane = tid & 31;
    const int warp = tid >> 5;                        // == head
    const int b    = blockIdx.x;
    const int g    = lane >> 2;                       // mma group (row in tile)
    const int tig  = lane & 3;                        // thread-in-group

    // ---- load obs row ----
    const float* rowp = gobs + (long)b * 1056;
    for (int i = tid; i < 1056; i += 128) obs[i] = __ldg(&rowp[i]);
    __syncthreads();

    // ---- alive mask + all-dead fix + pool count ----
    if (warp == 0) {
        float v = (obs[1024 + lane] >= 0.5f) ? 1.0f : 0.0f;
        float s = v;
#pragma unroll
        for (int o = 16; o; o >>= 1) s += __shfl_xor_sync(0xffffffffu, s, o);
        float vv = (s < 0.5f) ? 1.0f : v;
        alive[lane] = vv;
        if (lane == 0) {
            float cnt = (s < 0.5f) ? 32.0f : s;
            inv_cnt_sh = 1.0f / fmaxf(cnt, 1.0f);
        }
    }
    __syncthreads();

    // ---- token embedding ----
    if (warp < 2)
        embed_tokens<40>(obs + warp * 8 * 40, Wv, bv, xs, warp * 8, lane);
    else
        embed_tokens<24>(obs + 640 + (warp - 2) * 8 * 24, Wp, bp, xs, (warp - 2) * 8 + 16, lane);
    __syncthreads();          // xs + alive ready; obs (pbuf) dead

    for (int L = 0; L < 2; L++) {
        const float2* wsp = &g_wsplit[L][0] + warp * 32;     // this head's column band
        const float* asrc = L ? as1 : as0;
        const float* adst = L ? ad1 : ad0;

        // ---- GEMM: h = x @ w via tf32 mma, 3-term compensated. warp = head. ----
        float C[2][4][4];                    // [mtile][ntile][frag]
#pragma unroll
        for (int mt = 0; mt < 2; mt++)
#pragma unroll
            for (int nt = 0; nt < 4; nt++)
#pragma unroll
                for (int r = 0; r < 4; r++) C[mt][nt][r] = 0.f;

#pragma unroll 2
        for (int kb = 0; kb < 16; kb++) {
            // B fragments: precomputed {hi, lo} pairs, one LDG.64 each, no split ops
            const float2* wk = wsp + (kb * 8 + tig) * 128;
            float2 bf0[4], bf1[4];
#pragma unroll
            for (int nt = 0; nt < 4; nt++) {
                bf0[nt] = __ldg(&wk[nt * 8 + g]);
                bf1[nt] = __ldg(&wk[4 * 128 + nt * 8 + g]);
            }
            // A fragments, split hi/lo at read (x is dynamic)
            unsigned ah[2][4], al[2][4];
#pragma unroll
            for (int mt = 0; mt < 2; mt++) {
                const int r0 = (mt * 16 + g) * XSROW + kb * 8 + tig;
                split_tf32(xs[r0],                 ah[mt][0], al[mt][0]);
                split_tf32(xs[r0 + 8 * XSROW],     ah[mt][1], al[mt][1]);
                split_tf32(xs[r0 + 4],             ah[mt][2], al[mt][2]);
                split_tf32(xs[r0 + 8 * XSROW + 4], ah[mt][3], al[mt][3]);
            }
#pragma unroll
            for (int nt = 0; nt < 4; nt++) {
                const unsigned bh0 = __float_as_uint(bf0[nt].x);
                const unsigned bl0 = __float_as_uint(bf0[nt].y);
                const unsigned bh1 = __float_as_uint(bf1[nt].x);
                const unsigned bl1 = __float_as_uint(bf1[nt].y);
#pragma unroll
                for (int mt = 0; mt < 2; mt++) {
                    mma_tf32(C[mt][nt], ah[mt][0], ah[mt][1], ah[mt][2], ah[mt][3], bh0, bh1);
                    mma_tf32(C[mt][nt], ah[mt][0], ah[mt][1], ah[mt][2], ah[mt][3], bl0, bl1);
                    mma_tf32(C[mt][nt], al[mt][0], al[mt][1], al[mt][2], al[mt][3], bh0, bh1);
                }
            }
        }

        // ---- alpha from fragments: quad-reduce over tig ----
        {
            float sa[4] = {0.f, 0.f, 0.f, 0.f};
            float sd[4] = {0.f, 0.f, 0.f, 0.f};
#pragma unroll
            for (int nt = 0; nt < 4; nt++) {
                float2 av = __ldg((const float2*)&asrc[warp * 32 + nt * 8 + 2 * tig]);
                float2 dv = __ldg((const float2*)&adst[warp * 32 + nt * 8 + 2 * tig]);
#pragma unroll
                for (int mt = 0; mt < 2; mt++) {
                    sa[mt*2+0] += C[mt][nt][0] * av.x + C[mt][nt][1] * av.y;
                    sa[mt*2+1] += C[mt][nt][2] * av.x + C[mt][nt][3] * av.y;
                    sd[mt*2+0] += C[mt][nt][0] * dv.x + C[mt][nt][1] * dv.y;
                    sd[mt*2+1] += C[mt][nt][2] * dv.x + C[mt][nt][3] * dv.y;
                }
            }
#pragma unroll
            for (int tm = 0; tm < 4; tm++) {
                sa[tm] += __shfl_xor_sync(0xffffffffu, sa[tm], 1);
                sa[tm] += __shfl_xor_sync(0xffffffffu, sa[tm], 2);
                sd[tm] += __shfl_xor_sync(0xffffffffu, sd[tm], 1);
                sd[tm] += __shfl_xor_sync(0xffffffffu, sd[tm], 2);
                const int token = (tm >> 1) * 16 + (tm & 1) * 8 + g;
                as_sh[warp * 32 + token] = sa[tm];
                ad_sh[warp * 32 + token] = sd[tm];
            }
        }

        // ---- release xs (all warps finished GEMM reads), then store h into xs band ----
        __syncthreads();
#pragma unroll
        for (int mt = 0; mt < 2; mt++)
#pragma unroll
            for (int nt = 0; nt < 4; nt++) {
                float* hp = &xs[(mt * 16 + g) * XSROW + warp * 32 + nt * 8 + 2 * tig];
                *(float2*)hp               = make_float2(C[mt][nt][0], C[mt][nt][1]);
                *(float2*)(hp + 8 * XSROW) = make_float2(C[mt][nt][2], C[mt][nt][3]);
            }
        __syncwarp();

        // ---- softmax weights p (unnormalized) : lane = query i; kept in registers ----
        float p[32];
        {
            const int i = lane;
            const float a_i = as_sh[warp * 32 + i];
            float m = -1e30f;
#pragma unroll
            for (int j = 0; j < 32; j++) {
                float e = a_i + ad_sh[warp * 32 + j];
                e = fmaxf(e, 0.2f * e);                 // leaky relu
                p[j] = (alive[j] > 0.5f) ? e : -1e30f;  // mask
                m = fmaxf(m, p[j]);
            }
            float s = 0.f;
#pragma unroll
            for (int j = 0; j < 32; j++) { p[j] = __expf(p[j] - m); s += p[j]; }
            inv_sh[warp * 32 + i] = 1.0f / s;
        }

        // ---- aggregation: out = (p @ h) * inv, ELU; tf32 mma 2-term.
        //      pbuf holds 16 query-rows at a time (two phases). ----
        {
            float Dg[2][4][4];
#pragma unroll
            for (int mt = 0; mt < 2; mt++)
#pragma unroll
                for (int nt = 0; nt < 4; nt++)
#pragma unroll
                    for (int r = 0; r < 4; r++) Dg[mt][nt][r] = 0.f;

#pragma unroll
            for (int mt = 0; mt < 2; mt++) {
                // lanes [mt*16, mt*16+16) publish their p row into the half buffer
                if ((lane >> 4) == mt) {
                    float* pr = &pbuf[warp][lane & 15][0];
#pragma unroll
                    for (int q = 0; q < 8; q++)
                        *(float4*)&pr[q * 4] = make_float4(p[q*4], p[q*4+1], p[q*4+2], p[q*4+3]);
                }
                __syncwarp();
#pragma unroll
                for (int kb = 0; kb < 4; kb++) {
                    const float* pp = &pbuf[warp][g][kb * 8 + tig];
                    unsigned pa0 = hi_tf32(pp[0]);
                    unsigned pa1 = hi_tf32(pp[8 * PST]);
                    unsigned pa2 = hi_tf32(pp[4]);
                    unsigned pa3 = hi_tf32(pp[8 * PST + 4]);
#pragma unroll
                    for (int nt = 0; nt < 4; nt++) {
                        const int col = warp * 32 + nt * 8 + g;
                        float b0f = xs[(kb * 8 + tig) * XSROW + col];
                        float b1f = xs[(kb * 8 + tig + 4) * XSROW + col];
                        unsigned bh0, bl0, bh1, bl1;
                        split_tf32(b0f, bh0, bl0);
                        split_tf32(b1f, bh1, bl1);
                        mma_tf32(Dg[mt][nt], pa0, pa1, pa2, pa3, bh0, bh1);
                        mma_tf32(Dg[mt][nt], pa0, pa1, pa2, pa3, bl0, bl1);
                    }
                }
                __syncwarp();   // this half's pbuf reads done before next half rewrites
            }

            // normalize per query row, ELU, store back into the same xs band
#pragma unroll
            for (int mt = 0; mt < 2; mt++) {
                const float inv0 = inv_sh[warp * 32 + mt * 16 + g];
                const float inv1 = inv_sh[warp * 32 + mt * 16 + g + 8];
#pragma unroll
                for (int nt = 0; nt < 4; nt++) {
                    float* op = &xs[(mt * 16 + g) * XSROW + warp * 32 + nt * 8 + 2 * tig];
                    float o0 = elu1(Dg[mt][nt][0] * inv0);
                    float o1 = elu1(Dg[mt][nt][1] * inv0);
                    float o2 = elu1(Dg[mt][nt][2] * inv1);
                    float o3 = elu1(Dg[mt][nt][3] * inv1);
                    *(float2*)op               = make_float2(o0, o1);
                    *(float2*)(op + 8 * XSROW) = make_float2(o2, o3);
                }
            }
        }
        __syncthreads();   // all head bands rewritten before next GEMM / pool
    }

    // ---- masked mean pool: thread = output feature ----
    {
        float s = 0.f;
#pragma unroll
        for (int i = 0; i < 32; i++)
            s += alive[i] * xs[i * XSROW + tid];
        out[(long)b * 128 + tid] = s * inv_cnt_sh;
    }
}

extern "C" void kernel_launch(void* const* d_in, const int* in_sizes, int n_in,
                              void* d_out, int out_size)
{
    const float* gobs = (const float*)d_in[0];
    const float* Wv   = (const float*)d_in[1];
    const float* bv   = (const float*)d_in[2];
    const float* Wp   = (const float*)d_in[3];
    const float* bp   = (const float*)d_in[4];
    const float* w0   = (const float*)d_in[5];
    const float* as0  = (const float*)d_in[6];
    const float* ad0  = (const float*)d_in[7];
    const float* w1   = (const float*)d_in[8];
    const float* as1  = (const float*)d_in[9];
    const float* ad1  = (const float*)d_in[10];

    const int B = in_sizes[0] / 1056;

    split_weights_kernel<<<64, 256>>>(w0, w1);
    gnn_critic_kernel<<<B, 128>>>(gobs, Wv, bv, Wp, bp,
                                  as0, ad0, as1, ad1,
                                  (float*)d_out);
}